// round 1
// baseline (speedup 1.0000x reference)
#include <cuda_runtime.h>
#include <cstdint>

// Problem dims (fixed)
#define Bb 32
#define Ss 4096
#define Hh 512
#define Ee 512
#define NEGV -1000000000.0f

// ---------------- scratch (no allocations allowed) ----------------
__device__ float g_qpc[Bb * Hh];            // q_proj + bq + bk, per (b,h)
__device__ float g_ctxpart[8 * Bb * Ee];    // partial context sums (deterministic reduce)

// ---------------- helpers ----------------
__device__ __forceinline__ float tanh_fast(float x) {
    // tanh(x) = 1 - 2/(exp(2x)+1); safe at +-inf, ~2ulp from MUFU ex2
    float e = __expf(2.0f * x);
    return 1.0f - __fdividef(2.0f, e + 1.0f);
}

__device__ __forceinline__ unsigned long long pack2(float lo, float hi) {
    unsigned long long r;
    asm("mov.b64 %0, {%1, %2};" : "=l"(r) : "f"(lo), "f"(hi));
    return r;
}
__device__ __forceinline__ void unpack2(unsigned long long v, float& lo, float& hi) {
    asm("mov.b64 {%0, %1}, %2;" : "=f"(lo), "=f"(hi) : "l"(v));
}
__device__ __forceinline__ void fma2(unsigned long long& acc, unsigned long long a,
                                     unsigned long long b) {
    asm("fma.rn.f32x2 %0, %1, %2, %3;" : "=l"(acc) : "l"(a), "l"(b), "l"(acc));
}

// ---------------- K1: q_proj + bq + bk ----------------
__global__ void qproj_kernel(const float* __restrict__ query,
                             const float* __restrict__ Wq,
                             const float* __restrict__ bq,
                             const float* __restrict__ bk) {
    __shared__ float qs[Hh];
    int b = blockIdx.x;
    int h = threadIdx.x;
    qs[h] = query[b * Hh + h];
    __syncthreads();
    float acc = bq[h] + bk[h];
#pragma unroll 8
    for (int e = 0; e < Hh; e++) acc += qs[e] * Wq[e * Hh + h];
    g_qpc[b * Hh + h] = acc;
}

// ---------------- K2: fused scores GEMM ----------------
// Each block: 32 rows (one b) x full H=512 cols of k_proj, fused tanh*v reduce.
// f32x2 packed FMA: acc[8 rows][4 col-pairs] per thread; 256 threads = 4 rowgrp x 64 colgrp.
#define TM 32
#define KC 16

__global__ __launch_bounds__(256, 2) void scores_kernel(
    const float* __restrict__ keys, const float* __restrict__ Wk,
    const float* __restrict__ v, const int* __restrict__ mask,
    const float* __restrict__ bv, float* __restrict__ scores) {
    __shared__ unsigned long long As2[KC][TM + 1];  // pre-packed {a,a}
    __shared__ float Bs[KC][Hh];                    // Wk chunk
    __shared__ float red[64][33];                   // padded reduction buffer

    const int tid = threadIdx.x;
    const int cg = tid & 63;   // col group 0..63 (8 cols each)
    const int rg = tid >> 6;   // row group 0..3 (8 rows each)
    const int row0 = blockIdx.x * TM;      // global flattened (b,s) row
    const int b = row0 >> 12;              // / 4096

    unsigned long long acc[8][4];
#pragma unroll
    for (int i = 0; i < 8; i++)
#pragma unroll
        for (int j = 0; j < 4; j++) acc[i][j] = 0ull;

    for (int k0 = 0; k0 < Ee; k0 += KC) {
        // load A tile: 32 rows x KC, pre-pack to {a,a}
#pragma unroll
        for (int i = 0; i < 2; i++) {
            int idx = tid + i * 256;
            int r = idx >> 4, kk = idx & 15;
            float a = keys[(size_t)(row0 + r) * Ee + k0 + kk];
            As2[kk][r] = pack2(a, a);
        }
        // load B tile: KC x 512 floats = 2048 float4, 8 per thread
#pragma unroll
        for (int i = 0; i < 8; i++) {
            int idx = tid + i * 256;
            int krow = idx >> 7;
            int c4 = idx & 127;
            float4 w = *(const float4*)(Wk + (size_t)(k0 + krow) * Hh + c4 * 4);
            *(float4*)&Bs[krow][c4 * 4] = w;
        }
        __syncthreads();

#pragma unroll
        for (int kk = 0; kk < KC; kk++) {
            ulonglong2 b01 = *(const ulonglong2*)&Bs[kk][cg * 8];
            ulonglong2 b23 = *(const ulonglong2*)&Bs[kk][cg * 8 + 4];
            unsigned long long bb[4] = {b01.x, b01.y, b23.x, b23.y};
#pragma unroll
            for (int i = 0; i < 8; i++) {
                unsigned long long a2 = As2[kk][rg * 8 + i];
#pragma unroll
                for (int j = 0; j < 4; j++) fma2(acc[i][j], a2, bb[j]);
            }
        }
        __syncthreads();
    }

    // epilogue: score contribution = sum_h tanh(kp + qpc) * v[h]
    float qv[8], vv[8];
    {
        const float* qrow = g_qpc + b * Hh + cg * 8;
        const float* vrow = v + cg * 8;
#pragma unroll
        for (int j = 0; j < 8; j++) { qv[j] = qrow[j]; vv[j] = vrow[j]; }
    }
#pragma unroll
    for (int i = 0; i < 8; i++) {
        float psum = 0.0f;
#pragma unroll
        for (int jp = 0; jp < 4; jp++) {
            float lo, hi;
            unpack2(acc[i][jp], lo, hi);
            psum += tanh_fast(lo + qv[jp * 2]) * vv[jp * 2];
            psum += tanh_fast(hi + qv[jp * 2 + 1]) * vv[jp * 2 + 1];
        }
        red[cg][rg * 8 + i] = psum;
    }
    __syncthreads();
    if (tid < TM) {
        float s = bv[0];
#pragma unroll 8
        for (int c = 0; c < 64; c++) s += red[c][tid];
        int grow = row0 + tid;               // flattened (b,s)
        s = (mask[grow] == 0) ? NEGV : s;
        scores[grow] = s;
    }
}

// ---------------- K3: row softmax (in place on scores -> attn) ----------------
__global__ void softmax_kernel(float* __restrict__ attn) {
    __shared__ float buf[Ss];
    __shared__ float rtmp[32];
    __shared__ float rowstat;
    int b = blockIdx.x;
    int tid = threadIdx.x;  // 256
    float* row = attn + (size_t)b * Ss;

    float lmax = -3.4e38f;
#pragma unroll
    for (int i = 0; i < Ss / 256; i++) {
        float x = row[tid + i * 256];
        buf[tid + i * 256] = x;
        lmax = fmaxf(lmax, x);
    }
#pragma unroll
    for (int o = 16; o; o >>= 1) lmax = fmaxf(lmax, __shfl_xor_sync(~0u, lmax, o));
    if ((tid & 31) == 0) rtmp[tid >> 5] = lmax;
    __syncthreads();
    if (tid == 0) {
        float m = rtmp[0];
        for (int w = 1; w < 8; w++) m = fmaxf(m, rtmp[w]);
        rowstat = m;
    }
    __syncthreads();
    float m = rowstat;

    float lsum = 0.0f;
#pragma unroll
    for (int i = 0; i < Ss / 256; i++) {
        float e = __expf(buf[tid + i * 256] - m);
        buf[tid + i * 256] = e;
        lsum += e;
    }
#pragma unroll
    for (int o = 16; o; o >>= 1) lsum += __shfl_xor_sync(~0u, lsum, o);
    __syncthreads();
    if ((tid & 31) == 0) rtmp[tid >> 5] = lsum;
    __syncthreads();
    if (tid == 0) {
        float s = 0.0f;
        for (int w = 0; w < 8; w++) s += rtmp[w];
        rowstat = 1.0f / s;
    }
    __syncthreads();
    float inv = rowstat;
#pragma unroll
    for (int i = 0; i < Ss / 256; i++) row[tid + i * 256] = buf[tid + i * 256] * inv;
}

// ---------------- K4: context partials (attn @ keys), deterministic ----------------
__global__ void context_partial_kernel(const float* __restrict__ keys,
                                       const float* __restrict__ attn) {
    __shared__ float aw[512];
    int b = blockIdx.y;
    int chunk = blockIdx.x;  // 0..7
    int s0 = chunk * 512;
    int e = threadIdx.x;     // 512
    aw[e] = attn[(size_t)b * Ss + s0 + e];
    __syncthreads();
    const float* kp = keys + ((size_t)b * Ss + s0) * Ee + e;
    float acc = 0.0f;
#pragma unroll 8
    for (int s = 0; s < 512; s++) acc += aw[s] * kp[(size_t)s * Ee];
    g_ctxpart[(chunk * Bb + b) * Ee + e] = acc;
}

// ---------------- K5: reduce partials -> context ----------------
__global__ void context_reduce_kernel(float* __restrict__ ctx) {
    int b = blockIdx.x;
    int e = threadIdx.x;
    float acc = 0.0f;
#pragma unroll
    for (int c = 0; c < 8; c++) acc += g_ctxpart[(c * Bb + b) * Ee + e];
    ctx[b * Ee + e] = acc;
}

// ---------------- launch ----------------
extern "C" void kernel_launch(void* const* d_in, const int* in_sizes, int n_in,
                              void* d_out, int out_size) {
    const float* query = (const float*)d_in[0];
    const float* keys  = (const float*)d_in[1];
    const int*   mask  = (const int*)d_in[2];
    const float* Wq    = (const float*)d_in[3];
    const float* bq    = (const float*)d_in[4];
    const float* Wk    = (const float*)d_in[5];
    const float* bk    = (const float*)d_in[6];
    const float* v     = (const float*)d_in[7];
    const float* bv    = (const float*)d_in[8];

    float* out  = (float*)d_out;
    float* ctx  = out;                 // (B, E)
    float* attn = out + Bb * Ee;       // (B, S)

    qproj_kernel<<<Bb, Hh>>>(query, Wq, bq, bk);
    scores_kernel<<<(Bb * Ss) / TM, 256>>>(keys, Wk, v, mask, bv, attn);
    softmax_kernel<<<Bb, 256>>>(attn);
    {
        dim3 grid(8, Bb);
        context_partial_kernel<<<grid, 512>>>(keys, attn);
    }
    context_reduce_kernel<<<Bb, Ee>>>(ctx);
}

// round 3
// speedup vs baseline: 2.4334x; 2.4334x over previous
#include <cuda_runtime.h>
#include <cuda_bf16.h>
#include <cstdint>

#define Bb 32
#define Ss 4096
#define Hh 512
#define Ee 512
#define NEGV -1000000000.0f

// ---------------- scratch ----------------
__device__ float g_qpc[Bb * Hh];
__device__ float g_ctxpart[8 * Bb * Ee];
__device__ __align__(16) __nv_bfloat16 g_wkt_hi[Hh * Ee];   // Wk^T hi  [h][e]
__device__ __align__(16) __nv_bfloat16 g_wkt_lo[Hh * Ee];   // Wk^T lo  [h][e]

// ---------------- helpers ----------------
__device__ __forceinline__ uint32_t smem_u32(const void* p) {
    uint32_t a;
    asm("{ .reg .u64 t; cvta.to.shared.u64 t, %1; cvt.u32.u64 %0, t; }" : "=r"(a) : "l"(p));
    return a;
}
__device__ __forceinline__ uint32_t swz(uint32_t off) { return off ^ ((off >> 3) & 0x70); }

__device__ __forceinline__ float tanh_fast(float x) {
    float e = __expf(2.0f * x);
    return 1.0f - __fdividef(2.0f, e + 1.0f);
}

__device__ __forceinline__ void ldmx4(uint32_t& r0, uint32_t& r1, uint32_t& r2, uint32_t& r3,
                                      uint32_t addr) {
    asm volatile("ldmatrix.sync.aligned.m8n8.x4.shared.b16 {%0,%1,%2,%3}, [%4];"
                 : "=r"(r0), "=r"(r1), "=r"(r2), "=r"(r3) : "r"(addr));
}
__device__ __forceinline__ void mma16816(float* d, const uint32_t* a, uint32_t b0, uint32_t b1) {
    asm volatile(
        "mma.sync.aligned.m16n8k16.row.col.f32.bf16.bf16.f32 "
        "{%0,%1,%2,%3}, {%4,%5,%6,%7}, {%8,%9}, {%0,%1,%2,%3};"
        : "+f"(d[0]), "+f"(d[1]), "+f"(d[2]), "+f"(d[3])
        : "r"(a[0]), "r"(a[1]), "r"(a[2]), "r"(a[3]), "r"(b0), "r"(b1));
}

// ---------------- K0: transpose+convert Wk -> bf16 hi/lo (Wkt[h][e]) ----------------
__global__ void wkt_kernel(const float* __restrict__ Wk) {
    __shared__ float t[64][65];
    int e0 = (blockIdx.x >> 3) * 64, h0 = (blockIdx.x & 7) * 64;
    int tx = threadIdx.x & 63, ty = threadIdx.x >> 6;
#pragma unroll
    for (int i = 0; i < 16; i++) {
        int r = ty + i * 4;
        t[r][tx] = Wk[(size_t)(e0 + r) * Hh + h0 + tx];
    }
    __syncthreads();
#pragma unroll
    for (int i = 0; i < 16; i++) {
        int hr = ty + i * 4;
        float x = t[tx][hr];
        __nv_bfloat16 hi = __float2bfloat16(x);
        __nv_bfloat16 lo = __float2bfloat16(x - __bfloat162float(hi));
        g_wkt_hi[(size_t)(h0 + hr) * Ee + e0 + tx] = hi;
        g_wkt_lo[(size_t)(h0 + hr) * Ee + e0 + tx] = lo;
    }
}

// ---------------- K1: q_proj + bq + bk ----------------
__global__ void qproj_kernel(const float* __restrict__ query, const float* __restrict__ Wq,
                             const float* __restrict__ bq, const float* __restrict__ bk) {
    __shared__ float qs[Hh];
    int b = blockIdx.x, h = threadIdx.x;
    qs[h] = query[b * Hh + h];
    __syncthreads();
    float acc = bq[h] + bk[h];
#pragma unroll 8
    for (int e = 0; e < Hh; e++) acc += qs[e] * Wq[e * Hh + h];
    g_qpc[b * Hh + h] = acc;
}

// ---------------- K2: mma.sync scores kernel ----------------
// CTA: M=128 rows x full H (4 N-phases of 128). 8 warps = 4(M) x 2(N), warp tile m32n64.
#define MT 128
#define NP 128       // N per phase
#define KC 64        // K chunk
#define ST 16384     // stage bytes (128 rows x 128B)
#define O_AH 0
#define O_AL (2 * ST)
#define O_BH (4 * ST)
#define O_BL (6 * ST)
#define O_SQ (8 * ST)
#define O_SV (O_SQ + 2048)
#define O_RED (O_SV + 2048)
#define SMEM_TOTAL (O_RED + 1024 + 256)

__device__ __forceinline__ void load_tiles(char* smem, const float* __restrict__ keys,
                                           int row0, int n0, int k0, int buf) {
    const int tid = threadIdx.x;
    char* Ah = smem + O_AH + buf * ST;
    char* Al = smem + O_AL + buf * ST;
    char* Bh = smem + O_BH + buf * ST;
    char* Bl = smem + O_BL + buf * ST;
    // A: 128 rows x 64 k fp32 -> bf16 hi/lo
#pragma unroll
    for (int j = 0; j < 4; j++) {
        int s = tid + j * 256;
        int r = s >> 3, k8 = (s & 7) * 8;
        const float4* gp = (const float4*)(keys + (size_t)(row0 + r) * Ee + k0 + k8);
        float4 x0 = gp[0], x1 = gp[1];
        float xs[8] = {x0.x, x0.y, x0.z, x0.w, x1.x, x1.y, x1.z, x1.w};
        union { uint4 u; __nv_bfloat16 b[8]; } vh, vl;
#pragma unroll
        for (int i = 0; i < 8; i++) {
            __nv_bfloat16 h = __float2bfloat16(xs[i]);
            vh.b[i] = h;
            vl.b[i] = __float2bfloat16(xs[i] - __bfloat162float(h));
        }
        uint32_t off = swz((uint32_t)(r * 128 + k8 * 2));
        *(uint4*)(Ah + off) = vh.u;
        *(uint4*)(Al + off) = vl.u;
    }
    // B: 128 n x 64 k bf16 copies
#pragma unroll
    for (int j = 0; j < 4; j++) {
        int s = tid + j * 256;
        int n = s >> 3, k8 = (s & 7) * 8;
        size_t gidx = (size_t)(n0 + n) * Ee + k0 + k8;
        uint32_t off = swz((uint32_t)(n * 128 + k8 * 2));
        *(uint4*)(Bh + off) = *(const uint4*)(g_wkt_hi + gidx);
        *(uint4*)(Bl + off) = *(const uint4*)(g_wkt_lo + gidx);
    }
}

__global__ __launch_bounds__(256, 1) void scores_mma_kernel(
    const float* __restrict__ keys, const int* __restrict__ mask,
    const float* __restrict__ v, const float* __restrict__ bv,
    float* __restrict__ scores) {
    extern __shared__ char smem[];
    const uint32_t smem_base = smem_u32(smem);
    const int tid = threadIdx.x;
    const int lane = tid & 31;
    const int wid = tid >> 5;
    const int wm = wid >> 1;           // 0..3
    const int wn = wid & 1;            // 0..1
    const int m_off = wm * 32;
    const int n_off = wn * 64;
    const int row0 = blockIdx.x * MT;
    const int b = row0 >> 12;

    float* sq = (float*)(smem + O_SQ);
    float* sv = (float*)(smem + O_SV);
    sq[tid] = g_qpc[b * Hh + tid];
    sq[tid + 256] = g_qpc[b * Hh + tid + 256];
    sv[tid] = v[tid];
    sv[tid + 256] = v[tid + 256];

    const int jm = lane >> 3;          // ldmatrix matrix id
    const int rr = lane & 7;           // ldmatrix row within matrix

    float rs[4] = {0.f, 0.f, 0.f, 0.f};

    load_tiles(smem, keys, row0, 0, 0, 0);
    __syncthreads();

    for (int p = 0; p < 4; p++) {
        float acc[2][8][4];
#pragma unroll
        for (int f = 0; f < 2; f++)
#pragma unroll
            for (int j = 0; j < 8; j++)
#pragma unroll
                for (int q = 0; q < 4; q++) acc[f][j][q] = 0.f;

        for (int c = 0; c < 8; c++) {
            const int buf = c & 1;
            if (c < 7)
                load_tiles(smem, keys, row0, p * NP, (c + 1) * KC, (c + 1) & 1);
            else if (p < 3)
                load_tiles(smem, keys, row0, (p + 1) * NP, 0, 0);

            const uint32_t ah_base = smem_base + O_AH + buf * ST;
            const uint32_t al_base = smem_base + O_AL + buf * ST;
            const uint32_t bh_base = smem_base + O_BH + buf * ST;
            const uint32_t bl_base = smem_base + O_BL + buf * ST;

#pragma unroll
            for (int kk = 0; kk < 4; kk++) {
                const int k0l = kk * 16;
                uint32_t ahi[2][4], alo[2][4];
#pragma unroll
                for (int f = 0; f < 2; f++) {
                    uint32_t aoff =
                        swz((uint32_t)((m_off + f * 16 + (jm & 1) * 8 + rr) * 128 +
                                       (k0l + (jm >> 1) * 8) * 2));
                    ldmx4(ahi[f][0], ahi[f][1], ahi[f][2], ahi[f][3], ah_base + aoff);
                    ldmx4(alo[f][0], alo[f][1], alo[f][2], alo[f][3], al_base + aoff);
                }
#pragma unroll
                for (int q = 0; q < 4; q++) {
                    const int frag0 = 2 * q;
                    uint32_t boff =
                        swz((uint32_t)((n_off + (frag0 + (jm >> 1)) * 8 + rr) * 128 +
                                       (k0l + (jm & 1) * 8) * 2));
                    uint32_t bh0, bh1, bh2, bh3, bl0, bl1, bl2, bl3;
                    ldmx4(bh0, bh1, bh2, bh3, bh_base + boff);
                    ldmx4(bl0, bl1, bl2, bl3, bl_base + boff);
#pragma unroll
                    for (int f = 0; f < 2; f++) {
                        mma16816(acc[f][frag0], ahi[f], bh0, bh1);
                        mma16816(acc[f][frag0], ahi[f], bl0, bl1);
                        mma16816(acc[f][frag0], alo[f], bh0, bh1);
                        mma16816(acc[f][frag0 + 1], ahi[f], bh2, bh3);
                        mma16816(acc[f][frag0 + 1], ahi[f], bl2, bl3);
                        mma16816(acc[f][frag0 + 1], alo[f], bh2, bh3);
                    }
                }
            }
            __syncthreads();
        }

        // fold phase accums into per-thread row sums
#pragma unroll
        for (int f = 0; f < 2; f++)
#pragma unroll
            for (int j = 0; j < 8; j++) {
                const int col = p * NP + n_off + j * 8 + (lane & 3) * 2;
                const float q0 = sq[col], q1 = sq[col + 1];
                const float v0 = sv[col], v1 = sv[col + 1];
                rs[f * 2 + 0] += tanh_fast(acc[f][j][0] + q0) * v0 +
                                 tanh_fast(acc[f][j][1] + q1) * v1;
                rs[f * 2 + 1] += tanh_fast(acc[f][j][2] + q0) * v0 +
                                 tanh_fast(acc[f][j][3] + q1) * v1;
            }
    }

    // reduce across the 4 lanes sharing a row, then across the 2 N-warps
#pragma unroll
    for (int i = 0; i < 4; i++) {
        rs[i] += __shfl_xor_sync(~0u, rs[i], 1);
        rs[i] += __shfl_xor_sync(~0u, rs[i], 2);
    }
    float* red = (float*)(smem + O_RED);   // [128][2]
    if ((lane & 3) == 0) {
#pragma unroll
        for (int i = 0; i < 4; i++) {
            int r = m_off + (i >> 1) * 16 + (i & 1) * 8 + (lane >> 2);
            red[r * 2 + wn] = rs[i];
        }
    }
    __syncthreads();
    if (tid < MT) {
        float s = red[tid * 2] + red[tid * 2 + 1] + bv[0];
        int grow = row0 + tid;
        s = (mask[grow] == 0) ? NEGV : s;
        scores[grow] = s;
    }
}

// ---------------- K3: softmax ----------------
__global__ void softmax_kernel(float* __restrict__ attn) {
    __shared__ float buf[Ss];
    __shared__ float rtmp[32];
    __shared__ float rowstat;
    int b = blockIdx.x, tid = threadIdx.x;
    float* row = attn + (size_t)b * Ss;
    float lmax = -3.4e38f;
#pragma unroll
    for (int i = 0; i < Ss / 256; i++) {
        float x = row[tid + i * 256];
        buf[tid + i * 256] = x;
        lmax = fmaxf(lmax, x);
    }
#pragma unroll
    for (int o = 16; o; o >>= 1) lmax = fmaxf(lmax, __shfl_xor_sync(~0u, lmax, o));
    if ((tid & 31) == 0) rtmp[tid >> 5] = lmax;
    __syncthreads();
    if (tid == 0) {
        float m = rtmp[0];
        for (int w = 1; w < 8; w++) m = fmaxf(m, rtmp[w]);
        rowstat = m;
    }
    __syncthreads();
    float m = rowstat;
    float lsum = 0.0f;
#pragma unroll
    for (int i = 0; i < Ss / 256; i++) {
        float e = __expf(buf[tid + i * 256] - m);
        buf[tid + i * 256] = e;
        lsum += e;
    }
#pragma unroll
    for (int o = 16; o; o >>= 1) lsum += __shfl_xor_sync(~0u, lsum, o);
    __syncthreads();
    if ((tid & 31) == 0) rtmp[tid >> 5] = lsum;
    __syncthreads();
    if (tid == 0) {
        float s = 0.0f;
        for (int w = 0; w < 8; w++) s += rtmp[w];
        rowstat = 1.0f / s;
    }
    __syncthreads();
    float inv = rowstat;
#pragma unroll
    for (int i = 0; i < Ss / 256; i++) row[tid + i * 256] = buf[tid + i * 256] * inv;
}

// ---------------- K4/K5: context ----------------
__global__ void context_partial_kernel(const float* __restrict__ keys,
                                       const float* __restrict__ attn) {
    __shared__ float aw[512];
    int b = blockIdx.y;
    int chunk = blockIdx.x;  // 0..7
    int s0 = chunk * 512;
    int e = threadIdx.x;     // 512
    aw[e] = attn[(size_t)b * Ss + s0 + e];
    __syncthreads();
    const float* kp = keys + ((size_t)b * Ss + s0) * Ee + e;
    float acc = 0.0f;
#pragma unroll 8
    for (int s = 0; s < 512; s++) acc += aw[s] * kp[(size_t)s * Ee];
    g_ctxpart[(chunk * Bb + b) * Ee + e] = acc;
}

__global__ void context_reduce_kernel(float* __restrict__ ctx) {
    int b = blockIdx.x, e = threadIdx.x;
    float acc = 0.0f;
#pragma unroll
    for (int c = 0; c < 8; c++) acc += g_ctxpart[(c * Bb + b) * Ee + e];
    ctx[b * Ee + e] = acc;
}

extern "C" void kernel_launch(void* const* d_in, const int* in_sizes, int n_in,
                              void* d_out, int out_size) {
    const float* query = (const float*)d_in[0];
    const float* keys  = (const float*)d_in[1];
    const int*   mask  = (const int*)d_in[2];
    const float* Wq    = (const float*)d_in[3];
    const float* bq    = (const float*)d_in[4];
    const float* Wk    = (const float*)d_in[5];
    const float* bk    = (const float*)d_in[6];
    const float* v     = (const float*)d_in[7];
    const float* bv    = (const float*)d_in[8];

    float* out  = (float*)d_out;
    float* ctx  = out;
    float* attn = out + Bb * Ee;

    cudaFuncSetAttribute(scores_mma_kernel, cudaFuncAttributeMaxDynamicSharedMemorySize,
                         SMEM_TOTAL);

    wkt_kernel<<<64, 256>>>(Wk);
    qproj_kernel<<<Bb, Hh>>>(query, Wq, bq, bk);
    scores_mma_kernel<<<(Bb * Ss) / MT, 256, SMEM_TOTAL>>>(keys, mask, v, bv, attn);
    softmax_kernel<<<Bb, 256>>>(attn);
    {
        dim3 grid(8, Bb);
        context_partial_kernel<<<grid, 512>>>(keys, attn);
    }
    context_reduce_kernel<<<Bb, Ee>>>(ctx);
}